// round 6
// baseline (speedup 1.0000x reference)
#include <cuda_runtime.h>

// Output (1,64,64,64,32) fp32 = 2,097,152 float4 = 1,048,576 aligned f4-pairs.
// One thread per pair: f4 indices {2t, 2t+1} always lie in the same position
// octet (p = (2t)>>3 == (2t+1)>>3), so ONE gathered scalar serves both stores.
//   c = p & 63, r = (p>>6) & 63, z = p >> 12
//   src = in[ ((z_idx[z]*128 + row_idx[r])*128 + col_idx[c]) * 32 ]
// A warp writes 32 consecutive pairs = 1024 B fully contiguous (2 coalesced
// STG.128 bursts), the best-case stream for the L2 write port, which the
// R2-R5 experiments show is the binding ~1550 B/cyc (quarter-read-rate)
// bottleneck. Gather/index LDG count halved vs the 1-f4-per-thread kernel.

__global__ __launch_bounds__(256) void sds3d_kernel(
    const float* __restrict__ in,
    const int* __restrict__ z_idx,
    const int* __restrict__ row_idx,
    const int* __restrict__ col_idx,
    float4* __restrict__ out)
{
    unsigned t = blockIdx.x * 256u + threadIdx.x;   // 0 .. 1,048,575
    unsigned f = t << 1;                            // first f4 index of the pair
    unsigned p = f >> 3;                            // gathered position
    unsigned c = p & 63u;
    unsigned r = (p >> 6) & 63u;
    unsigned z = p >> 12;

    int zi = __ldg(&z_idx[z]);
    int ri = __ldg(&row_idx[r]);
    int ci = __ldg(&col_idx[c]);

    unsigned src = (((unsigned)zi * 128u + (unsigned)ri) * 128u + (unsigned)ci) * 32u;
    float v = __ldg(&in[src]);

    float4 o = make_float4(v, v, v, v);
    out[f]     = o;
    out[f + 1] = o;
}

extern "C" void kernel_launch(void* const* d_in, const int* in_sizes, int n_in,
                              void* d_out, int out_size)
{
    const float* in      = (const float*)d_in[0];
    const int*   z_idx   = (const int*)d_in[1];
    const int*   row_idx = (const int*)d_in[2];
    const int*   col_idx = (const int*)d_in[3];
    float4* out = (float4*)d_out;

    // 1,048,576 threads / 256 = 4096 blocks
    sds3d_kernel<<<4096, 256>>>(in, z_idx, row_idx, col_idx, out);
}

// round 7
// speedup vs baseline: 1.3499x; 1.3499x over previous
#include <cuda_runtime.h>

// Output (1,64,64,64,32) fp32 = 2,097,152 float4.
// K=2 independent chains per thread, chain stride S = 1,048,576 float4
// (= 131072 positions = 32 z-groups): r and c identical across the 2 chains
// (shared row/col index loads + shared partial address), only z differs
// (z0, z0+32). Each STG.128 is warp-dense: lane l of a warp writes
// consecutive f4 indices -> full 128B-line coverage per instruction
// (the R6 regression showed instruction-level density is what matters).
//
// position p = f4_index >> 3 ; c = p & 63, r = (p>>6) & 63, z = p >> 12
// src scalar = in[ ((z_idx[z]*128 + row_idx[r])*128 + col_idx[c]) * 32 ]

#define S_F4 1048576u   // 2097152 / 2

__global__ __launch_bounds__(256) void sds3d_kernel(
    const float* __restrict__ in,
    const int* __restrict__ z_idx,
    const int* __restrict__ row_idx,
    const int* __restrict__ col_idx,
    float4* __restrict__ out)
{
    unsigned tid = blockIdx.x * 256u + threadIdx.x;   // 0 .. S_F4-1
    unsigned p   = tid >> 3;                          // position 0..131071 (z0 in 0..31)
    unsigned c   = p & 63u;
    unsigned r   = (p >> 6) & 63u;
    unsigned z0  = p >> 12;                           // 0..31

    int ri = __ldg(&row_idx[r]);
    int ci = __ldg(&col_idx[c]);
    unsigned rc = (unsigned)ri * 128u + (unsigned)ci; // shared partial address

    int zi0 = __ldg(&z_idx[z0]);
    int zi1 = __ldg(&z_idx[z0 + 32u]);

    float v0 = __ldg(&in[((unsigned)zi0 * 16384u + rc) * 32u]);
    float v1 = __ldg(&in[((unsigned)zi1 * 16384u + rc) * 32u]);

    __stcs(&out[tid],        make_float4(v0, v0, v0, v0));
    __stcs(&out[tid + S_F4], make_float4(v1, v1, v1, v1));
}

extern "C" void kernel_launch(void* const* d_in, const int* in_sizes, int n_in,
                              void* d_out, int out_size)
{
    const float* in      = (const float*)d_in[0];
    const int*   z_idx   = (const int*)d_in[1];
    const int*   row_idx = (const int*)d_in[2];
    const int*   col_idx = (const int*)d_in[3];
    float4* out = (float4*)d_out;

    // S_F4 threads / 256 = 4096 blocks
    sds3d_kernel<<<S_F4 / 256, 256>>>(in, z_idx, row_idx, col_idx, out);
}